// round 3
// baseline (speedup 1.0000x reference)
#include <cuda_runtime.h>
#include <cstdint>

// LSTM decoder, persistent per-CTA recurrence.
// B=2048, L=64, H=128, 4H=512, O=64, T=512, fp32.
// Identity: x_t == h_t for t>=1  =>  gates = h @ (W_ih+W_hh)^T + (b_ih+b_hh).
// t==0: x=0 => gates = h0 @ W_hh^T + (b_ih+b_hh).

typedef unsigned long long ull;

#define B_   2048
#define Lq   64
#define Hq   128
#define G4   512
#define Oq   64
#define Tq   512
#define NP   7       // batch pairs per CTA (up to 14 slots)
#define HS   20      // h_s row stride in floats (80 bytes, 16B-aligned)

// Precomputed transposed weights, [k][row] layout:
//   g_Wc [k*512 + row] = W_ih[row][k] + W_hh[row][k]
//   g_Whh[k*512 + row] = W_hh[row][k]
__device__ float g_Wc [G4 * Hq];
__device__ float g_Whh[G4 * Hq];

// ---------- helpers ----------
__device__ __forceinline__ ull fma2(ull a, ull b, ull c) {
    ull d; asm("fma.rn.f32x2 %0, %1, %2, %3;" : "=l"(d) : "l"(a), "l"(b), "l"(c)); return d;
}
__device__ __forceinline__ ull dup2(float x) {
    ull d; asm("mov.b64 %0, {%1, %1};" : "=l"(d) : "f"(x)); return d;
}
__device__ __forceinline__ void unpk(ull a, float& lo, float& hi) {
    asm("mov.b64 {%0, %1}, %2;" : "=f"(lo), "=f"(hi) : "l"(a));
}
__device__ __forceinline__ void ldsv2(ull& a, ull& b, unsigned addr) {
    asm volatile("ld.shared.v2.u64 {%0, %1}, [%2];" : "=l"(a), "=l"(b) : "r"(addr));
}
__device__ __forceinline__ ull lds64(unsigned addr) {
    ull a; asm volatile("ld.shared.u64 %0, [%1];" : "=l"(a) : "r"(addr)); return a;
}
__device__ __forceinline__ unsigned sm_u32(const void* p) {
    unsigned r;
    asm("{ .reg .u64 t; cvta.to.shared.u64 t, %1; cvt.u32.u64 %0, t; }" : "=r"(r) : "l"(p));
    return r;
}
__device__ __forceinline__ float sigf(float x)   { return __fdividef(1.f, 1.f + __expf(-x)); }
__device__ __forceinline__ float tanhf2(float x) { return __fdividef(2.f, 1.f + __expf(-2.f * x)) - 1.f; }

// ---------- prep: build transposed combined weights ----------
__global__ void decoder_prep(const float* __restrict__ Wih, const float* __restrict__ Whh) {
    int i = blockIdx.x * blockDim.x + threadIdx.x;   // i = k*512 + row
    if (i < G4 * Hq) {
        int row = i & 511;
        int k   = i >> 9;
        float b = Whh[row * Hq + k];
        g_Wc [i] = Wih[row * Hq + k] + b;
        g_Whh[i] = b;
    }
}

// ---------- gate GEMM: gates[row][b] for rows {tid, tid+256}, 7 batch-pairs ----------
// FIRST: both row-halves stream W_hh^T from global (step 0).
// Otherwise: row0 from SMEM (Wc rows 0..255), row1 streams g_Wc rows 256..511 via L2.
template <bool FIRST>
__device__ __forceinline__ void gate_gemm(
    const float* __restrict__ gw0,   // g_Whh + tid         (used when FIRST)
    const float* __restrict__ gw1,   // gW    + tid + 256
    const float* __restrict__ ws0,   // Ws    + tid         (used when !FIRST)
    unsigned hb, ull bb0, ull bb1, ull (&a0)[NP], ull (&a1)[NP])
{
#pragma unroll
    for (int p = 0; p < NP; p++) { a0[p] = bb0; a1[p] = bb1; }
#pragma unroll 8
    for (int k = 0; k < Hq; k++) {
        float w0f = FIRST ? __ldg(gw0 + k * G4) : ws0[k * 256];
        float w1f = __ldg(gw1 + k * G4);
        ull w0 = dup2(w0f), w1 = dup2(w1f);
        unsigned a = hb + (unsigned)(k * (HS * 4));
        ull h0, h1, h2, h3, h4, h5, h6;
        ldsv2(h0, h1, a);            // slots 0..3
        ldsv2(h2, h3, a + 16);       // slots 4..7
        ldsv2(h4, h5, a + 32);       // slots 8..11
        h6 = lds64(a + 48);          // slots 12,13
        a0[0] = fma2(w0, h0, a0[0]);  a1[0] = fma2(w1, h0, a1[0]);
        a0[1] = fma2(w0, h1, a0[1]);  a1[1] = fma2(w1, h1, a1[1]);
        a0[2] = fma2(w0, h2, a0[2]);  a1[2] = fma2(w1, h2, a1[2]);
        a0[3] = fma2(w0, h3, a0[3]);  a1[3] = fma2(w1, h3, a1[3]);
        a0[4] = fma2(w0, h4, a0[4]);  a1[4] = fma2(w1, h4, a1[4]);
        a0[5] = fma2(w0, h5, a0[5]);  a1[5] = fma2(w1, h5, a1[5]);
        a0[6] = fma2(w0, h6, a0[6]);  a1[6] = fma2(w1, h6, a1[6]);
    }
}

// SMEM layout (float offsets):
//   Ws   [128][256] @ 0       (32768)  Wc rows 0..255 transposed [k][row]
//   Wos  [128][64]  @ 32768   ( 8192)  Wo transposed [k][o]
//   h_s  [128][20]  @ 40960   ( 2560)  h transposed [k][slot] (slots 14..19 pad)
//   c_s  [14][132]  @ 43520   ( 1848)
//   gt   [14][520]  @ 45368   ( 7280)  gates [slot][row]
#define OFF_WOS 32768
#define OFF_H   40960
#define OFF_C   43520
#define OFF_G   45368
#define SMEM_FLOATS 52648
#define SMEM_BYTES  (SMEM_FLOATS * 4)

__global__ void __launch_bounds__(256, 1) decoder_main(
    const float* __restrict__ latent, const float* __restrict__ fc_w, const float* __restrict__ fc_b,
    const float* __restrict__ b_ih,   const float* __restrict__ b_hh,
    const float* __restrict__ Wo,     const float* __restrict__ bo,
    float* __restrict__ out)
{
    extern __shared__ float sm[];
    float* Ws  = sm;
    float* Wos = sm + OFF_WOS;
    float* h_s = sm + OFF_H;
    float* c_s = sm + OFF_C;
    float* gt  = sm + OFF_G;

    const int tid = threadIdx.x;
    const int cta = blockIdx.x;
    int bstart, nb;
    if (cta < 124) { bstart = cta * 14;                nb = 14; }
    else           { bstart = 1736 + (cta - 124) * 13; nb = 13; }

    // Stage Wc rows 0..255 into SMEM (transposed [k][row]); coalesced reads.
    for (int i = tid; i < Hq * 256; i += 256) {
        int k = i >> 8, j = i & 255;
        Ws[i] = g_Wc[k * G4 + j];
    }
    // Wo transposed into SMEM: Wos[k*64+o] = Wo[o*128+k].
    for (int i = tid; i < Hq * Oq; i += 256) {
        int k = i >> 6, o = i & 63;
        Wos[i] = Wo[o * Hq + k];
    }
    // Zero h (incl. pad slots) and c.
    for (int i = tid; i < Hq * HS; i += 256) h_s[i] = 0.f;
    for (int i = tid; i < 14 * 132; i += 256) c_s[i] = 0.f;
    __syncthreads();

    // h0 = latent @ fc_w^T + fc_b  (padded slots stay 0)
    for (int i = tid; i < 14 * Hq; i += 256) {
        int slot = i >> 7, hk = i & 127;
        float acc = 0.f;
        if (slot < nb) {
            acc = fc_b[hk];
            const float* lp = latent + (size_t)(bstart + slot) * Lq;
            const float* wp = fc_w + hk * Lq;
#pragma unroll 8
            for (int l = 0; l < Lq; l++) acc += lp[l] * wp[l];
        }
        h_s[hk * HS + slot] = acc;
    }

    const float bias0 = b_ih[tid]       + b_hh[tid];
    const float bias1 = b_ih[tid + 256] + b_hh[tid + 256];
    const ull bb0 = dup2(bias0), bb1 = dup2(bias1);

    // Output phase: warps 0..6 -> batch pair bp = warp id; lane jj -> outputs 2jj, 2jj+1.
    const int jj = tid & 31;
    const int bp = tid >> 5;
    float bo0 = 0.f, bo1 = 0.f;
    if (tid < 224) { bo0 = bo[2 * jj]; bo1 = bo[2 * jj + 1]; }

    const unsigned hb = sm_u32(h_s);
    const float* gW0a = g_Whh + tid;
    const float* gW1a = g_Whh + tid + 256;
    const float* gW1b = g_Wc  + tid + 256;
    const float* ws0  = Ws + tid;
    __syncthreads();

    for (int t = 0; t < Tq; t++) {
        // ---- gate GEMM (reads h_s of previous step) ----
        ull a0[NP], a1[NP];
        if (t == 0) gate_gemm<true >(gW0a, gW1a, ws0, hb, bb0, bb1, a0, a1);
        else        gate_gemm<false>(gW0a, gW1b, ws0, hb, bb0, bb1, a0, a1);

        // ---- store gates: gt[slot][row] (conflict-free STS.32) ----
#pragma unroll
        for (int p = 0; p < NP; p++) {
            float l0, hi0, l1, hi1;
            unpk(a0[p], l0, hi0);
            unpk(a1[p], l1, hi1);
            gt[(2 * p    ) * 520 + tid      ] = l0;
            gt[(2 * p + 1) * 520 + tid      ] = hi0;
            gt[(2 * p    ) * 520 + tid + 256] = l1;
            gt[(2 * p + 1) * 520 + tid + 256] = hi1;
        }
        __syncthreads();

        // ---- elementwise LSTM cell (gate order i,f,g,o) ----
#pragma unroll
        for (int j = 0; j < 7; j++) {
            int idx = tid + j * 256;        // 0..1791 = 14 slots x 128
            int slot = idx >> 7, hh = idx & 127;
            const float* g = gt + slot * 520;
            float gi = g[hh], gf = g[hh + 128], gg = g[hh + 256], go = g[hh + 384];
            float c = c_s[slot * 132 + hh];
            float ci = sigf(gi), cf = sigf(gf), co = sigf(go), cg = tanhf2(gg);
            c = cf * c + ci * cg;
            float hv = co * tanhf2(c);
            c_s[slot * 132 + hh] = c;
            h_s[hh * HS + slot] = hv;
        }
        __syncthreads();

        // ---- out[b, t, :] = h @ Wo^T + bo   (warps 0..6) ----
        if (tid < 224) {
            ull ac0 = dup2(bo0), ac1 = dup2(bo1);
#pragma unroll 8
            for (int k = 0; k < Hq; k++) {
                ull h2 = lds64(hb + (unsigned)(k * (HS * 4) + bp * 8));  // h[k][2bp], h[k][2bp+1]
                float2 ww = *reinterpret_cast<const float2*>(Wos + k * 64 + 2 * jj);
                ac0 = fma2(dup2(ww.x), h2, ac0);
                ac1 = fma2(dup2(ww.y), h2, ac1);
            }
            float v00, v10, v01, v11;
            unpk(ac0, v00, v10);   // o=2jj   for (b0, b1)
            unpk(ac1, v01, v11);   // o=2jj+1 for (b0, b1)
            int b0 = bstart + 2 * bp;
            size_t base0 = ((size_t)b0 * Tq + t) * Oq + 2 * jj;
            *reinterpret_cast<float2*>(out + base0) = make_float2(v00, v01);
            if (2 * bp + 1 < nb) {
                *reinterpret_cast<float2*>(out + base0 + (size_t)Tq * Oq) = make_float2(v10, v11);
            }
        }
        // No barrier needed here: next gate_gemm reads h_s (fenced by the
        // post-elementwise barrier); gt is only rewritten after the next
        // iteration's first barrier, by which time all reads are done.
    }
}

extern "C" void kernel_launch(void* const* d_in, const int* in_sizes, int n_in,
                              void* d_out, int out_size) {
    const float* latent = (const float*)d_in[0];
    const float* fc_w   = (const float*)d_in[1];
    const float* fc_b   = (const float*)d_in[2];
    const float* W_ih   = (const float*)d_in[3];
    const float* W_hh   = (const float*)d_in[4];
    const float* b_ih   = (const float*)d_in[5];
    const float* b_hh   = (const float*)d_in[6];
    const float* Wo     = (const float*)d_in[7];
    const float* bo     = (const float*)d_in[8];
    float* out = (float*)d_out;

    cudaFuncSetAttribute(decoder_main,
                         cudaFuncAttributeMaxDynamicSharedMemorySize, SMEM_BYTES);

    decoder_prep<<<(G4 * Hq + 255) / 256, 256>>>(W_ih, W_hh);
    decoder_main<<<148, 256, SMEM_BYTES>>>(latent, fc_w, fc_b, b_ih, b_hh, Wo, bo, out);
}

// round 4
// speedup vs baseline: 1.1562x; 1.1562x over previous
#include <cuda_runtime.h>
#include <cstdint>

// LSTM decoder, persistent per-CTA recurrence, 512 threads, k-split GEMM.
// B=2048, L=64, H=128, 4H=512, O=64, T=512, fp32.
// Identity: x_t == h_t for t>=1  =>  gates = h @ (W_ih+W_hh)^T + (b_ih+b_hh).
// t==0: x=0 => gates = h0 @ W_hh^T + (b_ih+b_hh).

typedef unsigned long long ull;

#define Lq   64
#define Hq   128
#define G4   512
#define Oq   64
#define Tq   512
#define NP   7       // batch pairs per CTA (up to 14 slots)
#define HS   20      // h_s row stride in floats (80 B, 16B-aligned)
#define WSROWS 192   // gate-weight rows resident in SMEM

// Precomputed transposed weights, [k][row] layout:
//   g_Wc [k*512 + row] = W_ih[row][k] + W_hh[row][k]
//   g_Whh[k*512 + row] = W_hh[row][k]
__device__ float g_Wc [G4 * Hq];
__device__ float g_Whh[G4 * Hq];

// ---------- helpers ----------
__device__ __forceinline__ ull fma2(ull a, ull b, ull c) {
    ull d; asm("fma.rn.f32x2 %0, %1, %2, %3;" : "=l"(d) : "l"(a), "l"(b), "l"(c)); return d;
}
__device__ __forceinline__ ull dup2(float x) {
    ull d; asm("mov.b64 %0, {%1, %1};" : "=l"(d) : "f"(x)); return d;
}
__device__ __forceinline__ void unpk(ull a, float& lo, float& hi) {
    asm("mov.b64 {%0, %1}, %2;" : "=f"(lo), "=f"(hi) : "l"(a));
}
__device__ __forceinline__ void ldsv2(ull& a, ull& b, unsigned addr) {
    asm volatile("ld.shared.v2.u64 {%0, %1}, [%2];" : "=l"(a), "=l"(b) : "r"(addr));
}
__device__ __forceinline__ ull lds64(unsigned addr) {
    ull a; asm volatile("ld.shared.u64 %0, [%1];" : "=l"(a) : "r"(addr)); return a;
}
__device__ __forceinline__ unsigned sm_u32(const void* p) {
    unsigned r;
    asm("{ .reg .u64 t; cvta.to.shared.u64 t, %1; cvt.u32.u64 %0, t; }" : "=r"(r) : "l"(p));
    return r;
}
__device__ __forceinline__ float sigf(float x)   { return __fdividef(1.f, 1.f + __expf(-x)); }
__device__ __forceinline__ float tanhf2(float x) { return __fdividef(2.f, 1.f + __expf(-2.f * x)) - 1.f; }

// ---------- prep: build transposed combined weights ----------
__global__ void decoder_prep(const float* __restrict__ Wih, const float* __restrict__ Whh) {
    int i = blockIdx.x * blockDim.x + threadIdx.x;   // i = k*512 + row
    if (i < G4 * Hq) {
        int row = i & 511;
        int k   = i >> 9;
        float b = Whh[row * Hq + k];
        g_Wc [i] = Wih[row * Hq + k] + b;
        g_Whh[i] = b;
    }
}

// ---------- gate partial GEMM over 64 k's ----------
// Rows {r, r+256}; w0 (row r) from SMEM when USEWS, else streamed via L2.
// w1 (row r+256) always streamed. Pointers pre-offset by kbase.
template <bool USEWS>
__device__ __forceinline__ void gate_partial(
    const float* __restrict__ gw0, const float* __restrict__ gw1,
    const float* __restrict__ ws0, unsigned hbk,
    ull bi0, ull bi1, ull (&a0)[NP], ull (&a1)[NP])
{
#pragma unroll
    for (int p = 0; p < NP; p++) { a0[p] = bi0; a1[p] = bi1; }
#pragma unroll 8
    for (int k = 0; k < 64; k++) {
        float w0f = USEWS ? ws0[k * WSROWS] : __ldg(gw0 + k * G4);
        float w1f = __ldg(gw1 + k * G4);
        ull w0 = dup2(w0f), w1 = dup2(w1f);
        unsigned a = hbk + (unsigned)(k * (HS * 4));
        ull h0, h1, h2, h3, h4, h5, h6;
        ldsv2(h0, h1, a);            // slots 0..3
        ldsv2(h2, h3, a + 16);       // slots 4..7
        ldsv2(h4, h5, a + 32);       // slots 8..11
        h6 = lds64(a + 48);          // slots 12,13
        a0[0] = fma2(w0, h0, a0[0]);  a1[0] = fma2(w1, h0, a1[0]);
        a0[1] = fma2(w0, h1, a0[1]);  a1[1] = fma2(w1, h1, a1[1]);
        a0[2] = fma2(w0, h2, a0[2]);  a1[2] = fma2(w1, h2, a1[2]);
        a0[3] = fma2(w0, h3, a0[3]);  a1[3] = fma2(w1, h3, a1[3]);
        a0[4] = fma2(w0, h4, a0[4]);  a1[4] = fma2(w1, h4, a1[4]);
        a0[5] = fma2(w0, h5, a0[5]);  a1[5] = fma2(w1, h5, a1[5]);
        a0[6] = fma2(w0, h6, a0[6]);  a1[6] = fma2(w1, h6, a1[6]);
    }
}

// SMEM layout (float offsets):
//   Ws   [128][192] @ 0       (24576)  Wc rows 0..191 transposed [k][row]
//   Wos  [128][64]  @ 24576   ( 8192)  Wo transposed [k][o]
//   h_s  [128][20]  @ 32768   ( 2560)  h transposed [k][slot]
//   c_s  [14][132]  @ 35328   ( 1848)
//   gt   [14][520]  @ 37176   ( 7280)  lower-k gate partials (+bias)
//   pb   [14][520]  @ 44456   ( 7280)  upper-k gate partials
//   ob   [2][224][4]@ 51736   ( 1792)  out partials {ac0.lo, ac0.hi, ac1.lo, ac1.hi}
#define OFF_WOS 24576
#define OFF_H   32768
#define OFF_C   35328
#define OFF_G   37176
#define OFF_P   44456
#define OFF_O   51736
#define SMEM_FLOATS 53528
#define SMEM_BYTES  (SMEM_FLOATS * 4)

__global__ void __launch_bounds__(512, 1) decoder_main(
    const float* __restrict__ latent, const float* __restrict__ fc_w, const float* __restrict__ fc_b,
    const float* __restrict__ b_ih,   const float* __restrict__ b_hh,
    const float* __restrict__ Wo,     const float* __restrict__ bo,
    float* __restrict__ out)
{
    extern __shared__ float sm[];
    float* Ws  = sm;
    float* Wos = sm + OFF_WOS;
    float* h_s = sm + OFF_H;
    float* c_s = sm + OFF_C;
    float* gt  = sm + OFF_G;
    float* pb  = sm + OFF_P;
    float* ob  = sm + OFF_O;

    const int tid = threadIdx.x;
    const int r   = tid & 255;    // gate row base (rows r, r+256)
    const int kh  = tid >> 8;     // k-half: 0 -> k 0..63, 1 -> k 64..127
    const int cta = blockIdx.x;
    int bstart, nb;
    if (cta < 124) { bstart = cta * 14;                nb = 14; }
    else           { bstart = 1736 + (cta - 124) * 13; nb = 13; }

    // Stage Wc rows 0..191 into SMEM, transposed [k][r].
    for (int i = tid; i < Hq * WSROWS; i += 512) {
        int k = i / WSROWS, j = i - k * WSROWS;
        Ws[i] = g_Wc[k * G4 + j];
    }
    // Wo transposed into SMEM: Wos[k*64+o] = Wo[o*128+k].
    for (int i = tid; i < Hq * Oq; i += 512) {
        int k = i >> 6, o = i & 63;
        Wos[i] = Wo[o * Hq + k];
    }
    // Zero h (incl. pad slots) and c.
    for (int i = tid; i < Hq * HS; i += 512) h_s[i] = 0.f;
    for (int i = tid; i < 14 * 132; i += 512) c_s[i] = 0.f;
    __syncthreads();

    // h0 = latent @ fc_w^T + fc_b  (padded slots stay 0)
    for (int i = tid; i < 14 * Hq; i += 512) {
        int slot = i >> 7, hk = i & 127;
        float acc = 0.f;
        if (slot < nb) {
            acc = fc_b[hk];
            const float* lp = latent + (size_t)(bstart + slot) * Lq;
            const float* wp = fc_w + hk * Lq;
#pragma unroll 8
            for (int l = 0; l < Lq; l++) acc += lp[l] * wp[l];
        }
        h_s[hk * HS + slot] = acc;
    }

    // Biases (lower k-half carries them; upper initializes to 0).
    const float bias0 = b_ih[r]       + b_hh[r];
    const float bias1 = b_ih[r + 256] + b_hh[r + 256];
    const ull bi0 = kh ? 0ull : dup2(bias0);
    const ull bi1 = kh ? 0ull : dup2(bias1);
    float* gdst = kh ? pb : gt;

    // Output-GEMM roles: warps 0..13. warp w -> pair p = w%7, k-half okh = w/7.
    const int jj  = tid & 31;
    const int ow  = tid >> 5;
    const int op  = (ow < 7) ? ow : ow - 7;
    const int okh = (ow < 7) ? 0 : 1;
    float obo0 = 0.f, obo1 = 0.f;
    if (tid < 448 && okh == 0) { obo0 = bo[2 * jj]; obo1 = bo[2 * jj + 1]; }

    const unsigned hb  = sm_u32(h_s);
    const int kbase = kh * 64;
    const unsigned hbk = hb + (unsigned)(kbase * (HS * 4));
    const float* pWh0 = g_Whh + kbase * G4 + r;         // step-0 stream (row r)
    const float* pWh1 = g_Whh + kbase * G4 + r + 256;   // step-0 stream (row r+256)
    const float* pWc0 = g_Wc  + kbase * G4 + r;         // stream row r (r >= 192)
    const float* pWc1 = g_Wc  + kbase * G4 + r + 256;   // stream row r+256
    const float* pWs  = Ws + kbase * WSROWS + r;        // SMEM row r (r < 192)
    const float* wos  = Wos + okh * 64 * Oq + 2 * jj;
    const unsigned hob = hb + (unsigned)(okh * 64 * (HS * 4) + op * 8);
    __syncthreads();

    for (int t = 0; t < Tq; t++) {
        // ---- phase 1: gate partial GEMM (reads h_t) ----
        ull a0[NP], a1[NP];
        if (t == 0)            gate_partial<false>(pWh0, pWh1, pWs, hbk, bi0, bi1, a0, a1);
        else if (r < WSROWS)   gate_partial<true >(pWc0, pWc1, pWs, hbk, bi0, bi1, a0, a1);
        else                   gate_partial<false>(pWc0, pWc1, pWs, hbk, bi0, bi1, a0, a1);

#pragma unroll
        for (int p = 0; p < NP; p++) {
            float l0, hi0, l1, hi1;
            unpk(a0[p], l0, hi0);
            unpk(a1[p], l1, hi1);
            gdst[(2 * p    ) * 520 + r      ] = l0;
            gdst[(2 * p + 1) * 520 + r      ] = hi0;
            gdst[(2 * p    ) * 520 + r + 256] = l1;
            gdst[(2 * p + 1) * 520 + r + 256] = hi1;
        }

        // ---- phase 1b: out-GEMM partials for out[t-1] (reads same h_t) ----
        if (t > 0 && tid < 448) {
            ull ac0 = dup2(obo0), ac1 = dup2(obo1);
#pragma unroll 8
            for (int k = 0; k < 64; k++) {
                ull h2 = lds64(hob + (unsigned)(k * (HS * 4)));   // h[k][2op], h[k][2op+1]
                float2 ww = *reinterpret_cast<const float2*>(wos + k * Oq);
                ac0 = fma2(dup2(ww.x), h2, ac0);
                ac1 = fma2(dup2(ww.y), h2, ac1);
            }
            float x0, x1, x2, x3;
            unpk(ac0, x0, x1);
            unpk(ac1, x2, x3);
            float* od = ob + (okh * 224 + op * 32 + jj) * 4;
            od[0] = x0; od[1] = x1; od[2] = x2; od[3] = x3;
        }
        __syncthreads();

        // ---- phase 2: elementwise LSTM cell (sums both k-half partials) ----
#pragma unroll
        for (int j = 0; j < 4; j++) {
            int idx = tid + j * 512;        // 0..1791 = 14 slots x 128
            if (idx < 14 * Hq) {
                int slot = idx >> 7, hh = idx & 127;
                const float* g = gt + slot * 520;
                const float* q = pb + slot * 520;
                float gi = g[hh      ] + q[hh      ];
                float gf = g[hh + 128] + q[hh + 128];
                float gg = g[hh + 256] + q[hh + 256];
                float go = g[hh + 384] + q[hh + 384];
                float c = c_s[slot * 132 + hh];
                float ci = sigf(gi), cf = sigf(gf), co = sigf(go), cg = tanhf2(gg);
                c = cf * c + ci * cg;
                float hv = co * tanhf2(c);
                c_s[slot * 132 + hh] = c;
                h_s[hh * HS + slot] = hv;
            }
        }

        // ---- phase 2b: finish out[t-1] ----
        if (t > 0 && tid < 224) {
            int bp = tid >> 5;
            float4 lo4 = *reinterpret_cast<const float4*>(ob + (bp * 32 + jj) * 4);
            float4 up4 = *reinterpret_cast<const float4*>(ob + (224 + bp * 32 + jj) * 4);
            float v00 = lo4.x + up4.x;   // o=2jj,   b0
            float v10 = lo4.y + up4.y;   // o=2jj,   b1
            float v01 = lo4.z + up4.z;   // o=2jj+1, b0
            float v11 = lo4.w + up4.w;   // o=2jj+1, b1
            int b0 = bstart + 2 * bp;
            size_t base0 = ((size_t)b0 * Tq + (t - 1)) * Oq + 2 * jj;
            *reinterpret_cast<float2*>(out + base0) = make_float2(v00, v01);
            if (2 * bp + 1 < nb)
                *reinterpret_cast<float2*>(out + base0 + (size_t)Tq * Oq) = make_float2(v10, v11);
        }
        __syncthreads();
    }

    // ---- tail: out[T-1] from final h ----
    if (tid < 448) {
        ull ac0 = dup2(obo0), ac1 = dup2(obo1);
#pragma unroll 8
        for (int k = 0; k < 64; k++) {
            ull h2 = lds64(hob + (unsigned)(k * (HS * 4)));
            float2 ww = *reinterpret_cast<const float2*>(wos + k * Oq);
            ac0 = fma2(dup2(ww.x), h2, ac0);
            ac1 = fma2(dup2(ww.y), h2, ac1);
        }
        float x0, x1, x2, x3;
        unpk(ac0, x0, x1);
        unpk(ac1, x2, x3);
        float* od = ob + (okh * 224 + op * 32 + jj) * 4;
        od[0] = x0; od[1] = x1; od[2] = x2; od[3] = x3;
    }
    __syncthreads();
    if (tid < 224) {
        int bp = tid >> 5;
        float4 lo4 = *reinterpret_cast<const float4*>(ob + (bp * 32 + jj) * 4);
        float4 up4 = *reinterpret_cast<const float4*>(ob + (224 + bp * 32 + jj) * 4);
        int b0 = bstart + 2 * bp;
        size_t base0 = ((size_t)b0 * Tq + (Tq - 1)) * Oq + 2 * jj;
        *reinterpret_cast<float2*>(out + base0) = make_float2(lo4.x + up4.x, lo4.z + up4.z);
        if (2 * bp + 1 < nb)
            *reinterpret_cast<float2*>(out + base0 + (size_t)Tq * Oq) =
                make_float2(lo4.y + up4.y, lo4.w + up4.w);
    }
}

extern "C" void kernel_launch(void* const* d_in, const int* in_sizes, int n_in,
                              void* d_out, int out_size) {
    const float* latent = (const float*)d_in[0];
    const float* fc_w   = (const float*)d_in[1];
    const float* fc_b   = (const float*)d_in[2];
    const float* W_ih   = (const float*)d_in[3];
    const float* W_hh   = (const float*)d_in[4];
    const float* b_ih   = (const float*)d_in[5];
    const float* b_hh   = (const float*)d_in[6];
    const float* Wo     = (const float*)d_in[7];
    const float* bo     = (const float*)d_in[8];
    float* out = (float*)d_out;

    cudaFuncSetAttribute(decoder_main,
                         cudaFuncAttributeMaxDynamicSharedMemorySize, SMEM_BYTES);

    decoder_prep<<<(G4 * Hq + 511) / 512, 512>>>(W_ih, W_hh);
    decoder_main<<<148, 512, SMEM_BYTES>>>(latent, fc_w, fc_b, b_ih, b_hh, Wo, bo, out);
}

// round 5
// speedup vs baseline: 1.1843x; 1.0244x over previous
#include <cuda_runtime.h>
#include <cstdint>

// LSTM decoder, persistent per-CTA recurrence, 512 threads, k-split GEMM,
// pair-packed weights (1 load feeds rows r and r+256).
// B=2048, L=64, H=128, 4H=512, O=64, T=512, fp32.
// Identity: x_t == h_t for t>=1  =>  gates = h @ (W_ih+W_hh)^T + (b_ih+b_hh).
// t==0: x=0 => gates = h0 @ W_hh^T + (b_ih+b_hh).

typedef unsigned long long ull;

#define Lq   64
#define Hq   128
#define G4   512
#define Oq   64
#define Tq   512
#define NP   7       // batch pairs per CTA (up to 14 slots)
#define HS   20      // h_s row stride in floats (80 B = 5x16B, v2.u64-aligned)
#define KSM  48      // leading k's (of the kh=0 half) whose weight pairs sit in SMEM

// Pair-packed transposed weights, [k][r] layout, k in [0,128), r in [0,256):
//   g_Wp [k*256+r] = ( Wc[r][k],  Wc[r+256][k] )   with Wc = W_ih + W_hh
//   g_Whp[k*256+r] = ( Whh[r][k], Whh[r+256][k] )
__device__ float2 g_Wp [Hq * 256];
__device__ float2 g_Whp[Hq * 256];

// ---------- helpers ----------
__device__ __forceinline__ ull fma2(ull a, ull b, ull c) {
    ull d; asm("fma.rn.f32x2 %0, %1, %2, %3;" : "=l"(d) : "l"(a), "l"(b), "l"(c)); return d;
}
__device__ __forceinline__ ull dup2(float x) {
    ull d; asm("mov.b64 %0, {%1, %1};" : "=l"(d) : "f"(x)); return d;
}
__device__ __forceinline__ void unpk(ull a, float& lo, float& hi) {
    asm("mov.b64 {%0, %1}, %2;" : "=f"(lo), "=f"(hi) : "l"(a));
}
__device__ __forceinline__ void ldsv2(ull& a, ull& b, unsigned addr) {
    asm volatile("ld.shared.v2.u64 {%0, %1}, [%2];" : "=l"(a), "=l"(b) : "r"(addr));
}
__device__ __forceinline__ ull lds64(unsigned addr) {
    ull a; asm volatile("ld.shared.u64 %0, [%1];" : "=l"(a) : "r"(addr)); return a;
}
__device__ __forceinline__ unsigned sm_u32(const void* p) {
    unsigned r;
    asm("{ .reg .u64 t; cvta.to.shared.u64 t, %1; cvt.u32.u64 %0, t; }" : "=r"(r) : "l"(p));
    return r;
}
__device__ __forceinline__ float sigf(float x)   { return __fdividef(1.f, 1.f + __expf(-x)); }
__device__ __forceinline__ float tanhf2(float x) { return __fdividef(2.f, 1.f + __expf(-2.f * x)) - 1.f; }

// ---------- prep: build pair-packed transposed weights ----------
__global__ void decoder_prep(const float* __restrict__ Wih, const float* __restrict__ Whh) {
    int i = blockIdx.x * blockDim.x + threadIdx.x;   // i = k*256 + r
    if (i < Hq * 256) {
        int r = i & 255;
        int k = i >> 8;
        float b0 = Whh[r * Hq + k];
        float b1 = Whh[(r + 256) * Hq + k];
        g_Whp[i] = make_float2(b0, b1);
        g_Wp [i] = make_float2(Wih[r * Hq + k] + b0, Wih[(r + 256) * Hq + k] + b1);
    }
}

// ---------- one k-slice of the gate partial GEMM ----------
__device__ __forceinline__ void gate_k(float2 w, unsigned a, ull (&a0)[NP], ull (&a1)[NP]) {
    ull w0 = dup2(w.x), w1 = dup2(w.y);
    ull h0, h1, h2, h3, h4, h5, h6;
    ldsv2(h0, h1, a);            // slots 0..3
    ldsv2(h2, h3, a + 16);       // slots 4..7
    ldsv2(h4, h5, a + 32);       // slots 8..11
    h6 = lds64(a + 48);          // slots 12,13
    a0[0] = fma2(w0, h0, a0[0]);  a1[0] = fma2(w1, h0, a1[0]);
    a0[1] = fma2(w0, h1, a0[1]);  a1[1] = fma2(w1, h1, a1[1]);
    a0[2] = fma2(w0, h2, a0[2]);  a1[2] = fma2(w1, h2, a1[2]);
    a0[3] = fma2(w0, h3, a0[3]);  a1[3] = fma2(w1, h3, a1[3]);
    a0[4] = fma2(w0, h4, a0[4]);  a1[4] = fma2(w1, h4, a1[4]);
    a0[5] = fma2(w0, h5, a0[5]);  a1[5] = fma2(w1, h5, a1[5]);
    a0[6] = fma2(w0, h6, a0[6]);  a1[6] = fma2(w1, h6, a1[6]);
}

// Gate partial over 64 k's. First NSMEM k's read pair-weights from SMEM (wps),
// the rest stream pair-weights from global (gw). Pointers pre-offset by (kbase, r).
template <int NSMEM>
__device__ __forceinline__ void gate_partial(
    const float2* __restrict__ gw, const float2* __restrict__ wps,
    unsigned hbk, ull bi0, ull bi1, ull (&a0)[NP], ull (&a1)[NP])
{
#pragma unroll
    for (int p = 0; p < NP; p++) { a0[p] = bi0; a1[p] = bi1; }
#pragma unroll 8
    for (int k = 0; k < NSMEM; k++)
        gate_k(wps[k * 256], hbk + (unsigned)(k * (HS * 4)), a0, a1);
#pragma unroll 8
    for (int k = NSMEM; k < 64; k++)
        gate_k(__ldg(gw + k * 256), hbk + (unsigned)(k * (HS * 4)), a0, a1);
}

// SMEM layout (float offsets):
//   Wps  [48][256]f2 @ 0      (24576)  pair weights, k 0..47
//   Wos  [128][64]   @ 24576  ( 8192)  Wo transposed [k][o]
//   h_s  [128][20]   @ 32768  ( 2560)  h transposed [k][slot]
//   c_s  [14][132]   @ 35328  ( 1848)
//   gt   [14][520]   @ 37176  ( 7280)  kh=0 gate partials (+bias)
//   pb   [14][520]   @ 44456  ( 7280)  kh=1 gate partials
//   ob   [2][224][4] @ 51736  ( 1792)  out partials
#define OFF_WOS 24576
#define OFF_H   32768
#define OFF_C   35328
#define OFF_G   37176
#define OFF_P   44456
#define OFF_O   51736
#define SMEM_FLOATS 53528
#define SMEM_BYTES  (SMEM_FLOATS * 4)

__global__ void __launch_bounds__(512, 1) decoder_main(
    const float* __restrict__ latent, const float* __restrict__ fc_w, const float* __restrict__ fc_b,
    const float* __restrict__ b_ih,   const float* __restrict__ b_hh,
    const float* __restrict__ Wo,     const float* __restrict__ bo,
    float* __restrict__ out)
{
    extern __shared__ float sm[];
    float2* Wps = reinterpret_cast<float2*>(sm);
    float* Wos = sm + OFF_WOS;
    float* h_s = sm + OFF_H;
    float* c_s = sm + OFF_C;
    float* gt  = sm + OFF_G;
    float* pb  = sm + OFF_P;
    float* ob  = sm + OFF_O;

    const int tid = threadIdx.x;
    const int r   = tid & 255;    // gate row base (rows r, r+256)
    const int kh  = tid >> 8;     // k-half: 0 -> k 0..63, 1 -> k 64..127
    const int cta = blockIdx.x;
    int bstart, nb;
    if (cta < 124) { bstart = cta * 14;                nb = 14; }
    else           { bstart = 1736 + (cta - 124) * 13; nb = 13; }

    // Stage pair weights for k 0..47 (contiguous prefix of g_Wp).
    for (int i = tid; i < KSM * 256; i += 512) Wps[i] = g_Wp[i];
    // Wo transposed into SMEM: Wos[k*64+o] = Wo[o*128+k].
    for (int i = tid; i < Hq * Oq; i += 512) {
        int k = i >> 6, o = i & 63;
        Wos[i] = Wo[o * Hq + k];
    }
    // Zero h (incl. pad slots) and c.
    for (int i = tid; i < Hq * HS; i += 512) h_s[i] = 0.f;
    for (int i = tid; i < 14 * 132; i += 512) c_s[i] = 0.f;
    __syncthreads();

    // h0 = latent @ fc_w^T + fc_b  (padded slots stay 0)
    for (int i = tid; i < 14 * Hq; i += 512) {
        int slot = i >> 7, hk = i & 127;
        float acc = 0.f;
        if (slot < nb) {
            acc = fc_b[hk];
            const float* lp = latent + (size_t)(bstart + slot) * Lq;
            const float* wp = fc_w + hk * Lq;
#pragma unroll 8
            for (int l = 0; l < Lq; l++) acc += lp[l] * wp[l];
        }
        h_s[hk * HS + slot] = acc;
    }

    // Biases (kh=0 carries them; kh=1 initializes to 0).
    const float bias0 = b_ih[r]       + b_hh[r];
    const float bias1 = b_ih[r + 256] + b_hh[r + 256];
    const ull bi0 = kh ? 0ull : dup2(bias0);
    const ull bi1 = kh ? 0ull : dup2(bias1);
    float* gdst = kh ? pb : gt;

    // Output-GEMM roles: warps 0..13. warp w -> pair p = w%7, k-half okh = w/7.
    const int jj  = tid & 31;
    const int ow  = tid >> 5;
    const int op  = (ow < 7) ? ow : ow - 7;
    const int okh = (ow < 7) ? 0 : 1;
    float obo0 = 0.f, obo1 = 0.f;
    if (tid < 448 && okh == 0) { obo0 = bo[2 * jj]; obo1 = bo[2 * jj + 1]; }

    const unsigned hb  = sm_u32(h_s);
    const int kbase = kh * 64;
    const unsigned hbk = hb + (unsigned)(kbase * (HS * 4));
    const float2* pWc = g_Wp  + kbase * 256 + r;
    const float2* pWh = g_Whp + kbase * 256 + r;
    const float2* wps = Wps + r;
    const float* wos  = Wos + okh * 64 * Oq + 2 * jj;
    const unsigned hob = hb + (unsigned)(okh * 64 * (HS * 4) + op * 8);
    __syncthreads();

    for (int t = 0; t < Tq; t++) {
        // ---- phase 1: gate partial GEMM (reads h_s) ----
        ull a0[NP], a1[NP];
        if (t == 0)       gate_partial<0  >(pWh, wps, hbk, bi0, bi1, a0, a1);
        else if (kh == 0) gate_partial<KSM>(pWc, wps, hbk, bi0, bi1, a0, a1);
        else              gate_partial<0  >(pWc, wps, hbk, bi0, bi1, a0, a1);

#pragma unroll
        for (int p = 0; p < NP; p++) {
            float l0, hi0, l1, hi1;
            unpk(a0[p], l0, hi0);
            unpk(a1[p], l1, hi1);
            gdst[(2 * p    ) * 520 + r      ] = l0;
            gdst[(2 * p + 1) * 520 + r      ] = hi0;
            gdst[(2 * p    ) * 520 + r + 256] = l1;
            gdst[(2 * p + 1) * 520 + r + 256] = hi1;
        }

        // ---- phase 1b: out-GEMM partials for out[t-1] (reads same h_s) ----
        if (t > 0 && tid < 448) {
            ull ac0 = dup2(obo0), ac1 = dup2(obo1);
#pragma unroll 8
            for (int k = 0; k < 64; k++) {
                ull h2 = lds64(hob + (unsigned)(k * (HS * 4)));   // h[k][2op], h[k][2op+1]
                float2 ww = *reinterpret_cast<const float2*>(wos + k * Oq);
                ac0 = fma2(dup2(ww.x), h2, ac0);
                ac1 = fma2(dup2(ww.y), h2, ac1);
            }
            float x0, x1, x2, x3;
            unpk(ac0, x0, x1);
            unpk(ac1, x2, x3);
            float* od = ob + (okh * 224 + op * 32 + jj) * 4;
            od[0] = x0; od[1] = x1; od[2] = x2; od[3] = x3;
        }
        __syncthreads();

        // ---- phase 2: elementwise LSTM cell (sums both k-half partials) ----
#pragma unroll
        for (int j = 0; j < 4; j++) {
            int idx = tid + j * 512;        // 0..1791 = 14 slots x 128
            if (idx < 14 * Hq) {
                int slot = idx >> 7, hh = idx & 127;
                const float* g = gt + slot * 520;
                const float* q = pb + slot * 520;
                float gi = g[hh      ] + q[hh      ];
                float gf = g[hh + 128] + q[hh + 128];
                float gg = g[hh + 256] + q[hh + 256];
                float go = g[hh + 384] + q[hh + 384];
                float c = c_s[slot * 132 + hh];
                float ci = sigf(gi), cf = sigf(gf), co = sigf(go), cg = tanhf2(gg);
                c = cf * c + ci * cg;
                float hv = co * tanhf2(c);
                c_s[slot * 132 + hh] = c;
                h_s[hh * HS + slot] = hv;
            }
        }

        // ---- phase 2b: finish out[t-1] ----
        if (t > 0 && tid < 224) {
            int bp = tid >> 5;
            float4 lo4 = *reinterpret_cast<const float4*>(ob + (bp * 32 + jj) * 4);
            float4 up4 = *reinterpret_cast<const float4*>(ob + (224 + bp * 32 + jj) * 4);
            int b0 = bstart + 2 * bp;
            size_t base0 = ((size_t)b0 * Tq + (t - 1)) * Oq + 2 * jj;
            *reinterpret_cast<float2*>(out + base0) = make_float2(lo4.x + up4.x, lo4.z + up4.z);
            if (2 * bp + 1 < nb)
                *reinterpret_cast<float2*>(out + base0 + (size_t)Tq * Oq) =
                    make_float2(lo4.y + up4.y, lo4.w + up4.w);
        }
        __syncthreads();
    }

    // ---- tail: out[T-1] from final h ----
    if (tid < 448) {
        ull ac0 = dup2(obo0), ac1 = dup2(obo1);
#pragma unroll 8
        for (int k = 0; k < 64; k++) {
            ull h2 = lds64(hob + (unsigned)(k * (HS * 4)));
            float2 ww = *reinterpret_cast<const float2*>(wos + k * Oq);
            ac0 = fma2(dup2(ww.x), h2, ac0);
            ac1 = fma2(dup2(ww.y), h2, ac1);
        }
        float x0, x1, x2, x3;
        unpk(ac0, x0, x1);
        unpk(ac1, x2, x3);
        float* od = ob + (okh * 224 + op * 32 + jj) * 4;
        od[0] = x0; od[1] = x1; od[2] = x2; od[3] = x3;
    }
    __syncthreads();
    if (tid < 224) {
        int bp = tid >> 5;
        float4 lo4 = *reinterpret_cast<const float4*>(ob + (bp * 32 + jj) * 4);
        float4 up4 = *reinterpret_cast<const float4*>(ob + (224 + bp * 32 + jj) * 4);
        int b0 = bstart + 2 * bp;
        size_t base0 = ((size_t)b0 * Tq + (Tq - 1)) * Oq + 2 * jj;
        *reinterpret_cast<float2*>(out + base0) = make_float2(lo4.x + up4.x, lo4.z + up4.z);
        if (2 * bp + 1 < nb)
            *reinterpret_cast<float2*>(out + base0 + (size_t)Tq * Oq) =
                make_float2(lo4.y + up4.y, lo4.w + up4.w);
    }
}

extern "C" void kernel_launch(void* const* d_in, const int* in_sizes, int n_in,
                              void* d_out, int out_size) {
    const float* latent = (const float*)d_in[0];
    const float* fc_w   = (const float*)d_in[1];
    const float* fc_b   = (const float*)d_in[2];
    const float* W_ih   = (const float*)d_in[3];
    const float* W_hh   = (const float*)d_in[4];
    const float* b_ih   = (const float*)d_in[5];
    const float* b_hh   = (const float*)d_in[6];
    const float* Wo     = (const float*)d_in[7];
    const float* bo     = (const float*)d_in[8];
    float* out = (float*)d_out;

    cudaFuncSetAttribute(decoder_main,
                         cudaFuncAttributeMaxDynamicSharedMemorySize, SMEM_BYTES);

    decoder_prep<<<(Hq * 256 + 511) / 512, 512>>>(W_ih, W_hh);
    decoder_main<<<148, 512, SMEM_BYTES>>>(latent, fc_w, fc_b, b_ih, b_hh, Wo, bo, out);
}